// round 7
// baseline (speedup 1.0000x reference)
#include <cuda_runtime.h>
#include <cuda_bf16.h>
#include <stdint.h>
#include <math.h>

#define Bb   4
#define Nn   4096
#define Dd   512
#define Hh   8
#define DHd  64
#define Mm   266
#define BHh  32
#define BNn  16384
#define K2   1536      // big-GEMM split K (hi|lo|hi)
#define PK   192       // phi split K (hi|lo|hi of 64)
#define PN   320       // td column stride (padded)
#define NROWS ((size_t)BHh * Nn)   // 131072

// -------------------- scratch --------------------
__device__ float g_q  [NROWS * DHd];
__device__ float g_k  [NROWS * DHd];
__device__ float g_v  [NROWS * DHd];
__device__ float g_qp [NROWS * Mm];
__device__ float g_kp [NROWS * Mm];
__device__ float g_ctx [(size_t)BHh * Mm * DHd];
__device__ float g_ksum[BHh * Mm];
__device__ float g_kmax[BHh];
__device__ float g_diagq[NROWS];
__device__ float g_diagk[NROWS];
__device__ float g_dinv[NROWS];
__device__ float g_tdq[NROWS * PN];
__device__ float g_tdk[NROWS * PN];
__device__ __nv_bfloat16 g_qx[NROWS * PK];
__device__ __nv_bfloat16 g_kx[NROWS * PK];
__device__ __nv_bfloat16 g_projB[384 * PK];

__device__ __nv_bfloat16 g_x2   [(size_t)BNn * K2];
__device__ __nv_bfloat16 g_attn2[(size_t)BNn * K2];
__device__ __nv_bfloat16 g_wq2  [(size_t)Dd * K2];
__device__ __nv_bfloat16 g_wk2  [(size_t)Dd * K2];
__device__ __nv_bfloat16 g_wv2  [(size_t)Dd * K2];
__device__ __nv_bfloat16 g_wo2  [(size_t)Dd * K2];

// -------------------- helpers --------------------
__device__ __forceinline__ uint32_t smem_to_u32(const void* p) {
    uint32_t a;
    asm("{ .reg .u64 t; cvta.to.shared.u64 t, %1; cvt.u32.u64 %0, t; }"
        : "=r"(a) : "l"(p));
    return a;
}

#define CP_ASYNC16(dst, src) \
    asm volatile("cp.async.cg.shared.global [%0], [%1], 16;" \
                 :: "r"(dst), "l"(src) : "memory")
#define CP_COMMIT()  asm volatile("cp.async.commit_group;" ::: "memory")
#define CP_WAIT1()   asm volatile("cp.async.wait_group 1;" ::: "memory")
#define CP_WAIT0()   asm volatile("cp.async.wait_group 0;" ::: "memory")

__device__ __forceinline__ void ldm_x4(uint32_t& r0, uint32_t& r1,
                                       uint32_t& r2, uint32_t& r3, uint32_t addr) {
    asm volatile("ldmatrix.sync.aligned.m8n8.x4.shared.b16 {%0,%1,%2,%3}, [%4];"
                 : "=r"(r0), "=r"(r1), "=r"(r2), "=r"(r3) : "r"(addr));
}

__device__ __forceinline__ void mma16816(float* c, const uint32_t* a, const uint32_t* b) {
    asm volatile(
        "mma.sync.aligned.m16n8k16.row.col.f32.bf16.bf16.f32 "
        "{%0,%1,%2,%3}, {%4,%5,%6,%7}, {%8,%9}, {%0,%1,%2,%3};"
        : "+f"(c[0]), "+f"(c[1]), "+f"(c[2]), "+f"(c[3])
        : "r"(a[0]), "r"(a[1]), "r"(a[2]), "r"(a[3]), "r"(b[0]), "r"(b[1]));
}

__device__ __forceinline__ void atomicMaxF(float* addr, float val) {
    int* ai = (int*)addr;
    int old = *ai;
    while (__int_as_float(old) < val) {
        int assumed = old;
        old = atomicCAS(ai, assumed, __float_as_int(val));
        if (old == assumed) break;
    }
}

__device__ __forceinline__ float fast_exp(float x) {
    float y = fmaxf(x * 1.4426950408889634f, -126.0f);
    float r = rintf(y);
    float f = y - r;
    float p = 1.5403530e-4f;
    p = fmaf(p, f, 1.3333558e-3f);
    p = fmaf(p, f, 9.6181291e-3f);
    p = fmaf(p, f, 5.5504109e-2f);
    p = fmaf(p, f, 2.4022651e-1f);
    p = fmaf(p, f, 6.9314718e-1f);
    p = fmaf(p, f, 1.0f);
    int e = (int)r;
    float s = __int_as_float((e + 127) << 23);
    return p * s;
}

__device__ __forceinline__ uint32_t packbf(float a, float b) {
    __nv_bfloat162 t;
    t.x = __float2bfloat16(a);
    t.y = __float2bfloat16(b);
    return *(uint32_t*)&t;
}

#define NORMALIZER 0.35355339059327373f
#define RATIO      0.061313934f
#define EPSF       1e-4f

// -------------------- init --------------------
__global__ void k_init() {
    int i = blockIdx.x * 256 + threadIdx.x;
    if (i < BHh * Mm * DHd) g_ctx[i]  = 0.0f;
    if (i < BHh * Mm)       g_ksum[i] = 0.0f;
    if (i < BHh)            g_kmax[i] = -3.0e38f;
}

// -------------------- fp32 -> split bf16 for big GEMMs --------------------
__global__ __launch_bounds__(256) void k_split(const float* __restrict__ src,
                                               __nv_bfloat16* __restrict__ dst,
                                               int nrows, int loOff, int dupOff) {
    int i = blockIdx.x * 256 + threadIdx.x;
    if (i >= nrows * 128) return;
    int r = i >> 7;
    int c = (i & 127) << 2;
    float4 v = *(const float4*)(src + (size_t)r * 512 + c);
    __nv_bfloat16 h0 = __float2bfloat16(v.x), h1 = __float2bfloat16(v.y);
    __nv_bfloat16 h2 = __float2bfloat16(v.z), h3 = __float2bfloat16(v.w);
    __nv_bfloat16 l0 = __float2bfloat16(v.x - __bfloat162float(h0));
    __nv_bfloat16 l1 = __float2bfloat16(v.y - __bfloat162float(h1));
    __nv_bfloat16 l2 = __float2bfloat16(v.z - __bfloat162float(h2));
    __nv_bfloat16 l3 = __float2bfloat16(v.w - __bfloat162float(h3));
    size_t rb = (size_t)r * K2;
    __nv_bfloat162 H01; H01.x = h0; H01.y = h1;
    __nv_bfloat162 H23; H23.x = h2; H23.y = h3;
    __nv_bfloat162 L01; L01.x = l0; L01.y = l1;
    __nv_bfloat162 L23; L23.x = l2; L23.y = l3;
    *(__nv_bfloat162*)(dst + rb + c)              = H01;
    *(__nv_bfloat162*)(dst + rb + c + 2)          = H23;
    *(__nv_bfloat162*)(dst + rb + loOff + c)      = L01;
    *(__nv_bfloat162*)(dst + rb + loOff + c + 2)  = L23;
    *(__nv_bfloat162*)(dst + rb + dupOff + c)     = H01;
    *(__nv_bfloat162*)(dst + rb + dupOff + c + 2) = H23;
}

// -------------------- projB: proj[266,64] -> [384][192] bf16 hi|hi|lo, zero pad ----
__global__ __launch_bounds__(256) void k_projB(const float* __restrict__ proj) {
    int i = blockIdx.x * 256 + threadIdx.x;
    if (i >= 384 * 64) return;
    int m = i >> 6, c = i & 63;
    float v = (m < Mm) ? proj[m * 64 + c] : 0.f;
    __nv_bfloat16 h = __float2bfloat16(v);
    __nv_bfloat16 l = __float2bfloat16(v - __bfloat162float(h));
    g_projB[m * PK + c]        = h;
    g_projB[m * PK + 64 + c]   = h;
    g_projB[m * PK + 128 + c]  = l;
}

// -------------------- prep: q/k -> scaled split rows [hi|lo|hi], diag -------------
__global__ __launch_bounds__(256) void k_prep(int sel) {
    const float* src = sel ? g_k : g_q;
    __nv_bfloat16* dst = sel ? g_kx : g_qx;
    float* diag = sel ? g_diagk : g_diagq;
    int gid = blockIdx.x * 256 + threadIdx.x;   // NROWS*8 total
    int row = gid >> 3, sub = gid & 7;
    const float* s = src + (size_t)row * 64 + sub * 8;
    float4 a = *(const float4*)s;
    float4 b = *(const float4*)(s + 4);
    a.x *= NORMALIZER; a.y *= NORMALIZER; a.z *= NORMALIZER; a.w *= NORMALIZER;
    b.x *= NORMALIZER; b.y *= NORMALIZER; b.z *= NORMALIZER; b.w *= NORMALIZER;
    float ss = a.x * a.x + a.y * a.y + a.z * a.z + a.w * a.w
             + b.x * b.x + b.y * b.y + b.z * b.z + b.w * b.w;
    ss += __shfl_xor_sync(0xffffffffu, ss, 1);
    ss += __shfl_xor_sync(0xffffffffu, ss, 2);
    ss += __shfl_xor_sync(0xffffffffu, ss, 4);
    if (sub == 0) diag[row] = 0.5f * ss;
    uint4 H, L;
    H.x = packbf(a.x, a.y); H.y = packbf(a.z, a.w);
    H.z = packbf(b.x, b.y); H.w = packbf(b.z, b.w);
    __nv_bfloat162 h0 = *(__nv_bfloat162*)&H.x;
    __nv_bfloat162 h1 = *(__nv_bfloat162*)&H.y;
    __nv_bfloat162 h2 = *(__nv_bfloat162*)&H.z;
    __nv_bfloat162 h3 = *(__nv_bfloat162*)&H.w;
    L.x = packbf(a.x - __bfloat162float(h0.x), a.y - __bfloat162float(h0.y));
    L.y = packbf(a.z - __bfloat162float(h1.x), a.w - __bfloat162float(h1.y));
    L.z = packbf(b.x - __bfloat162float(h2.x), b.y - __bfloat162float(h2.y));
    L.w = packbf(b.z - __bfloat162float(h3.x), b.w - __bfloat162float(h3.y));
    __nv_bfloat16* d = dst + (size_t)row * PK + sub * 8;
    *(uint4*)d          = H;
    *(uint4*)(d + 64)   = L;
    *(uint4*)(d + 128)  = H;
}

// -------------------- big GEMM (validated) --------------------
#define ASTR 40
#define TILE_B (128 * ASTR)

#define LOAD_TILE(buf, t) do {                                         \
    uint32_t _o = (uint32_t)(buf) * (TILE_B * 2);                      \
    const __nv_bfloat16* _a = Arow + (t) * 32;                         \
    const __nv_bfloat16* _b = Brow + (t) * 32;                         \
    CP_ASYNC16(sAdst + _o,      _a);                                   \
    CP_ASYNC16(sAdst + _o + 16, _a + 8);                               \
    CP_ASYNC16(sBdst + _o,      _b);                                   \
    CP_ASYNC16(sBdst + _o + 16, _b + 8);                               \
} while (0)

#define MMA_BODY(ab, bb) do {                                                            \
    for (int ks = 0; ks < 32; ks += 16) {                                                \
        uint32_t a[2][4];                                                                \
        for (int mt = 0; mt < 2; mt++) {                                                 \
            uint32_t addr = (ab) +                                                       \
                (uint32_t)((m0 + mt * 16 + (lane & 15)) * ASTR + ks + ((lane >> 4) << 3)) * 2; \
            ldm_x4(a[mt][0], a[mt][1], a[mt][2], a[mt][3], addr);                        \
        }                                                                                \
        uint32_t b[8][2];                                                                \
        for (int p = 0; p < 4; p++) {                                                    \
            uint32_t addr = (bb) +                                                       \
                (uint32_t)((n0 + p * 16 + (lane & 7) + ((lane >> 4) << 3)) * ASTR + ks + (lane & 8)) * 2; \
            ldm_x4(b[2 * p][0], b[2 * p][1], b[2 * p + 1][0], b[2 * p + 1][1], addr);    \
        }                                                                                \
        for (int mt = 0; mt < 2; mt++)                                                   \
            for (int nt = 0; nt < 8; nt++)                                               \
                mma16816(acc[mt][nt], a[mt], b[nt]);                                     \
    }                                                                                    \
} while (0)

__global__ __launch_bounds__(256) void k_gemm(const __nv_bfloat16* __restrict__ A,
                                              const __nv_bfloat16* __restrict__ Bw,
                                              float* __restrict__ C,
                                              const float* __restrict__ xres,
                                              const float* __restrict__ bo,
                                              int finalmode) {
    __shared__ __nv_bfloat16 sA[2][TILE_B];
    __shared__ __nv_bfloat16 sB[2][TILE_B];
    int tid = threadIdx.x, lane = tid & 31, w = tid >> 5;
    int m0 = (w & 3) * 32, n0 = (w >> 2) * 64;
    int r0 = blockIdx.x * 128, e0 = blockIdx.y * 128;
    uint32_t sAu = smem_to_u32(sA), sBu = smem_to_u32(sB);

    float acc[2][8][4];
#pragma unroll
    for (int i = 0; i < 2; i++)
#pragma unroll
        for (int j = 0; j < 8; j++)
#pragma unroll
            for (int l = 0; l < 4; l++) acc[i][j][l] = 0.f;

    int lrow = tid >> 1, lcol = (tid & 1) << 4;
    const __nv_bfloat16* Arow = A + (size_t)(r0 + lrow) * K2 + lcol;
    const __nv_bfloat16* Brow = Bw + (size_t)(e0 + lrow) * K2 + lcol;
    uint32_t sAdst = sAu + (uint32_t)(lrow * ASTR + lcol) * 2;
    uint32_t sBdst = sBu + (uint32_t)(lrow * ASTR + lcol) * 2;

    LOAD_TILE(0, 0);
    CP_COMMIT();
    const int NT = K2 / 32;
#pragma unroll 1
    for (int t = 0; t < NT; ++t) {
        int buf = t & 1;
        if (t + 1 < NT) { LOAD_TILE(buf ^ 1, t + 1); CP_COMMIT(); CP_WAIT1(); }
        else           { CP_WAIT0(); }
        __syncthreads();
        uint32_t ab = sAu + (uint32_t)buf * (TILE_B * 2);
        uint32_t bb = sBu + (uint32_t)buf * (TILE_B * 2);
        MMA_BODY(ab, bb);
        __syncthreads();
    }

    int gid = lane >> 2, tig = lane & 3;
#pragma unroll
    for (int mt = 0; mt < 2; mt++) {
#pragma unroll
        for (int nt = 0; nt < 8; nt++) {
            int r = r0 + m0 + mt * 16 + gid;
            int e = e0 + n0 + nt * 8 + tig * 2;
            float2 v01 = make_float2(acc[mt][nt][0], acc[mt][nt][1]);
            float2 v23 = make_float2(acc[mt][nt][2], acc[mt][nt][3]);
            if (!finalmode) {
                int b = r >> 12, n = r & 4095;
                int h = e >> 6, dh = e & 63;
                float* d0 = C + (((size_t)((b << 3) + h) * Nn + n) * DHd + dh);
                *(float2*)d0 = v01;
                *(float2*)(d0 + 8 * DHd) = v23;
            } else {
                size_t b0 = (size_t)r * Dd + e;
                float2 x0 = *(const float2*)(xres + b0);
                float2 x1 = *(const float2*)(xres + b0 + 8 * Dd);
                float2 bv = *(const float2*)(bo + e);
                *(float2*)(C + b0) = make_float2(x0.x + bv.x + v01.x, x0.y + bv.y + v01.y);
                *(float2*)(C + b0 + 8 * Dd) = make_float2(x1.x + bv.x + v23.x, x1.y + bv.y + v23.y);
            }
        }
    }
}

// -------------------- phi GEMM: td[131072,320] = X[131072,192] @ projB^T -----------
__global__ __launch_bounds__(256) void k_phi(int sel) {
    __shared__ __nv_bfloat16 sA[2][TILE_B];
    __shared__ __nv_bfloat16 sB[2][TILE_B];
    __shared__ float smax;
    const __nv_bfloat16* A = sel ? g_kx : g_qx;
    float* td = sel ? g_tdk : g_tdq;
    int tid = threadIdx.x, lane = tid & 31, w = tid >> 5;
    int m0 = (w & 3) * 32, n0 = (w >> 2) * 64;
    int r0 = blockIdx.x * 128, e0 = blockIdx.y * 128;
    uint32_t sAu = smem_to_u32(sA), sBu = smem_to_u32(sB);
    if (tid == 0) smax = -3.0e38f;

    float acc[2][8][4];
#pragma unroll
    for (int i = 0; i < 2; i++)
#pragma unroll
        for (int j = 0; j < 8; j++)
#pragma unroll
            for (int l = 0; l < 4; l++) acc[i][j][l] = 0.f;

    int lrow = tid >> 1, lcol = (tid & 1) << 4;
    const __nv_bfloat16* Arow = A + (size_t)(r0 + lrow) * PK + lcol;
    const __nv_bfloat16* Brow = g_projB + (size_t)(e0 + lrow) * PK + lcol;
    uint32_t sAdst = sAu + (uint32_t)(lrow * ASTR + lcol) * 2;
    uint32_t sBdst = sBu + (uint32_t)(lrow * ASTR + lcol) * 2;

    LOAD_TILE(0, 0);
    CP_COMMIT();
    const int NT = PK / 32;   // 6
#pragma unroll 1
    for (int t = 0; t < NT; ++t) {
        int buf = t & 1;
        if (t + 1 < NT) { LOAD_TILE(buf ^ 1, t + 1); CP_COMMIT(); CP_WAIT1(); }
        else           { CP_WAIT0(); }
        __syncthreads();
        uint32_t ab = sAu + (uint32_t)buf * (TILE_B * 2);
        uint32_t bb = sBu + (uint32_t)buf * (TILE_B * 2);
        MMA_BODY(ab, bb);
        __syncthreads();
    }

    int gid = lane >> 2, tig = lane & 3;
    float mymax = -3.0e38f;
#pragma unroll
    for (int mt = 0; mt < 2; mt++) {
#pragma unroll
        for (int nt = 0; nt < 8; nt++) {
            int r = r0 + m0 + mt * 16 + gid;
            int e = e0 + n0 + nt * 8 + tig * 2;
            if (e < PN) {
                *(float2*)(td + (size_t)r * PN + e) =
                    make_float2(acc[mt][nt][0], acc[mt][nt][1]);
                *(float2*)(td + (size_t)(r + 8) * PN + e) =
                    make_float2(acc[mt][nt][2], acc[mt][nt][3]);
            }
            if (e < Mm) {
                mymax = fmaxf(mymax, fmaxf(fmaxf(acc[mt][nt][0], acc[mt][nt][1]),
                                           fmaxf(acc[mt][nt][2], acc[mt][nt][3])));
            }
        }
    }
    if (sel) {
        atomicMaxF(&smax, mymax);
        __syncthreads();
        if (tid == 0) atomicMaxF(&g_kmax[blockIdx.x >> 5], smax);
    }
}

// -------------------- exp_k: kp = ratio*(exp(td-diag-mx)+eps), ksum ---------------
__global__ __launch_bounds__(256) void k_exp_k() {
    __shared__ float diag_s[64];
    int tid = threadIdx.x, n0 = blockIdx.x * 64, bh = blockIdx.y;
    size_t gr0 = (size_t)bh * Nn + n0;
    if (tid < 64) diag_s[tid] = g_diagk[gr0 + tid];
    __syncthreads();
    float mx = g_kmax[bh];
    for (int m = tid; m < Mm; m += 256) {
        float cs = 0.f;
#pragma unroll 4
        for (int r = 0; r < 64; r++) {
            float t = g_tdk[(gr0 + r) * PN + m];
            float v = RATIO * (fast_exp(t - diag_s[r] - mx) + EPSF);
            g_kp[(gr0 + r) * Mm + m] = v;
            cs += v;
        }
        atomicAdd(&g_ksum[bh * Mm + m], cs);
    }
}

// -------------------- exp_q: rowmax, qp, dinv --------------------
__global__ __launch_bounds__(256) void k_exp_q() {
    __shared__ float ksum_s[Mm];
    int tid = threadIdx.x, n0 = blockIdx.x * 64, bh = blockIdx.y;
    size_t gr0 = (size_t)bh * Nn + n0;
    for (int i = tid; i < Mm; i += 256) ksum_s[i] = g_ksum[bh * Mm + i];
    __syncthreads();
    int row = tid >> 2, l4 = tid & 3;
    size_t gr = gr0 + row;
    const float* tdr = g_tdq + gr * PN;
    float pm = -3.0e38f;
    for (int m = l4; m < Mm; m += 4) pm = fmaxf(pm, tdr[m]);
    pm = fmaxf(pm, __shfl_xor_sync(0xffffffffu, pm, 1));
    pm = fmaxf(pm, __shfl_xor_sync(0xffffffffu, pm, 2));
    float dg = g_diagq[gr];
    float sum = 0.f;
    for (int m = l4; m < Mm; m += 4) {
        float v = RATIO * (fast_exp(tdr[m] - dg - pm) + EPSF);
        g_qp[gr * Mm + m] = v;
        sum += v * ksum_s[m];
    }
    sum += __shfl_xor_sync(0xffffffffu, sum, 1);
    sum += __shfl_xor_sync(0xffffffffu, sum, 2);
    if (l4 == 0) g_dinv[gr] = 1.0f / sum;
}

// -------------------- context: ctx[m,dh] += sum_n kp[n,m]*v[n,dh] --------------------
__global__ __launch_bounds__(256) void k_ctx() {
    __shared__ float Ksm[64][68];
    __shared__ float Vs[64][68];
    int tid = threadIdx.x;
    int m0 = blockIdx.x * 64;
    int nc = blockIdx.y * 512;
    int bh = blockIdx.z;
    float acc[4][4];
#pragma unroll
    for (int i = 0; i < 4; i++)
#pragma unroll
        for (int j = 0; j < 4; j++) acc[i][j] = 0.f;
    int ty = tid >> 4, tx = tid & 15;

    for (int n0 = nc; n0 < nc + 512; n0 += 64) {
#pragma unroll
        for (int i = 0; i < 16; i++) {
            int s = tid + i * 256;
            int n = s >> 6, mm = s & 63;
            Ksm[n][mm] = (m0 + mm < Mm)
                             ? g_kp[((size_t)bh * Nn + n0 + n) * Mm + m0 + mm]
                             : 0.f;
        }
#pragma unroll
        for (int i = 0; i < 4; i++) {
            int s = tid + i * 256;
            int n = s >> 4, c = (s & 15) << 2;
            float4 v = *(const float4*)(g_v + ((size_t)bh * Nn + n0 + n) * DHd + c);
            Vs[n][c] = v.x; Vs[n][c + 1] = v.y; Vs[n][c + 2] = v.z; Vs[n][c + 3] = v.w;
        }
        __syncthreads();
#pragma unroll
        for (int kk = 0; kk < 64; kk++) {
            float4 a = *(const float4*)&Ksm[kk][ty * 4];
            float4 b = *(const float4*)&Vs[kk][tx * 4];
            float ar[4] = {a.x, a.y, a.z, a.w};
            float br[4] = {b.x, b.y, b.z, b.w};
#pragma unroll
            for (int i = 0; i < 4; i++)
#pragma unroll
                for (int j = 0; j < 4; j++) acc[i][j] = fmaf(ar[i], br[j], acc[i][j]);
        }
        __syncthreads();
    }
#pragma unroll
    for (int i = 0; i < 4; i++) {
        int m = m0 + ty * 4 + i;
        if (m < Mm)
#pragma unroll
            for (int j = 0; j < 4; j++)
                atomicAdd(&g_ctx[((size_t)bh * Mm + m) * DHd + tx * 4 + j], acc[i][j]);
    }
}

// -------------------- out: attn2 (split bf16) --------------------
__global__ __launch_bounds__(256) void k_out() {
    __shared__ float Qs[64][68];
    __shared__ float Cs[64][68];
    int tid = threadIdx.x;
    int n0 = blockIdx.x * 64;
    int bh = blockIdx.y;
    float acc[4][4];
#pragma unroll
    for (int i = 0; i < 4; i++)
#pragma unroll
        for (int j = 0; j < 4; j++) acc[i][j] = 0.f;
    int ty = tid >> 4, tx = tid & 15;

    for (int c0 = 0; c0 < Mm; c0 += 64) {
#pragma unroll
        for (int i = 0; i < 16; i++) {
            int s = tid + i * 256;
            int r = s >> 6, kc = s & 63;
            Qs[kc][r] = (c0 + kc < Mm)
                            ? g_qp[((size_t)bh * Nn + n0 + r) * Mm + c0 + kc]
                            : 0.f;
        }
#pragma unroll
        for (int i = 0; i < 16; i++) {
            int s = tid + i * 256;
            int kk = s >> 6, dh = s & 63;
            Cs[kk][dh] = (c0 + kk < Mm)
                             ? g_ctx[((size_t)bh * Mm + c0 + kk) * DHd + dh]
                             : 0.f;
        }
        __syncthreads();
#pragma unroll
        for (int kk = 0; kk < 64; kk++) {
            float4 a = *(const float4*)&Qs[kk][ty * 4];
            float4 b = *(const float4*)&Cs[kk][tx * 4];
            float ar[4] = {a.x, a.y, a.z, a.w};
            float br[4] = {b.x, b.y, b.z, b.w};
#pragma unroll
            for (int i = 0; i < 4; i++)
#pragma unroll
                for (int j = 0; j < 4; j++) acc[i][j] = fmaf(ar[i], br[j], acc[i][j]);
        }
        __syncthreads();
    }
    int b = bh >> 3, h = bh & 7;
#pragma unroll
    for (int i = 0; i < 4; i++) {
        int n = n0 + ty * 4 + i;
        float dv = g_dinv[(size_t)bh * Nn + n];
        size_t rb = (size_t)(b * Nn + n) * K2 + h * 64 + tx * 4;
#pragma unroll
        for (int j = 0; j < 4; j++) {
            float val = acc[i][j] * dv;
            __nv_bfloat16 hv = __float2bfloat16(val);
            __nv_bfloat16 lv = __float2bfloat16(val - __bfloat162float(hv));
            g_attn2[rb + j]        = hv;
            g_attn2[rb + 512 + j]  = lv;
            g_attn2[rb + 1024 + j] = hv;
        }
    }
}

// -------------------- launch --------------------
extern "C" void kernel_launch(void* const* d_in, const int* in_sizes, int n_in,
                              void* d_out, int out_size) {
    const float* x    = (const float*)d_in[0];
    const float* Wq   = (const float*)d_in[1];
    const float* Wk   = (const float*)d_in[2];
    const float* Wv   = (const float*)d_in[3];
    const float* Wo   = (const float*)d_in[4];
    const float* bo   = (const float*)d_in[5];
    const float* proj = (const float*)d_in[6];
    float* out = (float*)d_out;
    (void)in_sizes; (void)n_in; (void)out_size;

    __nv_bfloat16 *x2p, *wq2p, *wk2p, *wv2p, *wo2p, *attn2p;
    cudaGetSymbolAddress((void**)&x2p, g_x2);
    cudaGetSymbolAddress((void**)&wq2p, g_wq2);
    cudaGetSymbolAddress((void**)&wk2p, g_wk2);
    cudaGetSymbolAddress((void**)&wv2p, g_wv2);
    cudaGetSymbolAddress((void**)&wo2p, g_wo2);
    cudaGetSymbolAddress((void**)&attn2p, g_attn2);
    float *qp_, *kp_, *vp_;
    cudaGetSymbolAddress((void**)&qp_, g_q);
    cudaGetSymbolAddress((void**)&kp_, g_k);
    cudaGetSymbolAddress((void**)&vp_, g_v);

    k_init<<<(BHh * Mm * DHd + 255) / 256, 256>>>();

    k_split<<<(BNn * 128 + 255) / 256, 256>>>(x, x2p, BNn, 512, 1024);
    k_split<<<(Dd * 128 + 255) / 256, 256>>>(Wq, wq2p, Dd, 1024, 512);
    k_split<<<(Dd * 128 + 255) / 256, 256>>>(Wk, wk2p, Dd, 1024, 512);
    k_split<<<(Dd * 128 + 255) / 256, 256>>>(Wv, wv2p, Dd, 1024, 512);
    k_split<<<(Dd * 128 + 255) / 256, 256>>>(Wo, wo2p, Dd, 1024, 512);
    k_projB<<<(384 * 64 + 255) / 256, 256>>>(proj);

    dim3 gG(BNn / 128, Dd / 128);
    k_gemm<<<gG, 256>>>(x2p, wq2p, qp_, nullptr, nullptr, 0);
    k_gemm<<<gG, 256>>>(x2p, wk2p, kp_, nullptr, nullptr, 0);
    k_gemm<<<gG, 256>>>(x2p, wv2p, vp_, nullptr, nullptr, 0);

    k_prep<<<(int)(NROWS * 8 / 256), 256>>>(0);
    k_prep<<<(int)(NROWS * 8 / 256), 256>>>(1);
    k_phi<<<dim3((int)(NROWS / 128), 3), 256>>>(1);
    k_phi<<<dim3((int)(NROWS / 128), 3), 256>>>(0);
    k_exp_k<<<dim3(Nn / 64, BHh), 256>>>();
    k_exp_q<<<dim3(Nn / 64, BHh), 256>>>();

    k_ctx<<<dim3(5, Nn / 512, BHh), 256>>>();
    k_out<<<dim3(Nn / 64, BHh), 256>>>();

    k_gemm<<<gG, 256>>>(attn2p, wo2p, out, x, bo, 1);
}